// round 13
// baseline (speedup 1.0000x reference)
#include <cuda_runtime.h>
#include <cuda_fp16.h>
#include <cstdint>

#define BB 256
#define HH 512
#define SS 512
#define H3 1536

// ---------------- scratch ----------------
__device__ float g_hnew[BB * HH];
__device__ float g_hc[BB * HH];
__device__ float g_scores[BB * SS];
__device__ float g_cd2[BB * HH];

// pre-converted fp16 operands
__device__ __half g_st_hi[BB * HH * SS];
__device__ __half g_dy_hi[BB * HH * SS];
__device__ __half g_Wab_hi[HH * 1024];
__device__ __half g_Wd_hi[HH * HH];

// ---------------- math ----------------
__device__ __forceinline__ float my_tanh(float x) {
    float ax = fabsf(x);
    float e = __expf(-2.0f * ax);
    float r = __fdividef(1.0f - e, 1.0f + e);
    return copysignf(r, x);
}
__device__ __forceinline__ float fast_tanh(float x) {
    float r;
    asm("tanh.approx.f32 %0, %1;" : "=f"(r) : "f"(x));
    return r;
}
__device__ __forceinline__ float my_sigmoid(float x) {
    return 1.0f / (1.0f + __expf(-x));
}

// ---------------- PTX helpers ----------------
__device__ __forceinline__ uint32_t smem_u32(const void* p) {
    uint32_t a;
    asm("{ .reg .u64 t; cvta.to.shared.u64 t, %1; cvt.u32.u64 %0, t; }" : "=r"(a) : "l"(p));
    return a;
}
__device__ __forceinline__ void cp16(uint32_t dst, const void* src) {
    asm volatile("cp.async.cg.shared.global [%0], [%1], 16;" :: "r"(dst), "l"(src));
}
#define CP_COMMIT() asm volatile("cp.async.commit_group;" ::: "memory")
#define CP_WAIT(n)  asm volatile("cp.async.wait_group %0;" :: "n"(n) : "memory")

__device__ __forceinline__ void ldm_x4(uint32_t* r, uint32_t a) {
    asm volatile("ldmatrix.sync.aligned.m8n8.x4.shared.b16 {%0,%1,%2,%3}, [%4];"
        : "=r"(r[0]), "=r"(r[1]), "=r"(r[2]), "=r"(r[3]) : "r"(a));
}
__device__ __forceinline__ void ldm_x2t(uint32_t* r, uint32_t a) {
    asm volatile("ldmatrix.sync.aligned.m8n8.x2.trans.shared.b16 {%0,%1}, [%2];"
        : "=r"(r[0]), "=r"(r[1]) : "r"(a));
}
__device__ __forceinline__ void mma_fp16(float* d, const uint32_t* a, const uint32_t* b) {
    asm volatile(
        "mma.sync.aligned.m16n8k16.row.col.f32.f16.f16.f32 "
        "{%0,%1,%2,%3}, {%4,%5,%6,%7}, {%8,%9}, {%0,%1,%2,%3};"
        : "+f"(d[0]), "+f"(d[1]), "+f"(d[2]), "+f"(d[3])
        : "r"(a[0]), "r"(a[1]), "r"(a[2]), "r"(a[3]), "r"(b[0]), "r"(b[1]));
}

// ---------------- tile config (units: fp16 halves) ----------------
#define TK 32
#define A_SH 40
#define B_SH 136
#define A_HALVES (128 * A_SH)           /* 5120 */
#define B_HALVES (TK * B_SH)            /* 4352 */
#define BH_OFF A_HALVES
#define STAGE_HALVES (A_HALVES + B_HALVES) /* 9472 */
#define SMEM_BYTES (2 * STAGE_HALVES * 2 + 256 * 4) /* 38912 */

// ---------------- prep: all fp32->fp16 conversions in one pass ----------------
__global__ void prep_all(const float* __restrict__ st, const float* __restrict__ dy,
                         const float* __restrict__ attn_W,
                         const float* __restrict__ dec_W) {
    const size_t NGE = 2ull * 16777216ull;  // encoder float4 groups (st + dy)
    const size_t NGW = 196608ull;           // weight float4 groups
    size_t nth = (size_t)gridDim.x * blockDim.x;
    for (size_t g = (size_t)blockIdx.x * blockDim.x + threadIdx.x; g < NGE + NGW;
         g += nth) {
        const float* srcp;
        __half* dstp;
        if (g < NGE) {
            bool isdy = g >= 16777216ull;
            size_t off = (g & 16777215ull) * 4;
            srcp = (isdy ? dy : st) + off;
            dstp = (isdy ? g_dy_hi : g_st_hi) + off;
        } else {
            size_t gw = g - NGE;
            if (gw < 131072ull) {  // Wab: [512][1024] from attn_W cols 0..1023
                size_t e = gw * 4;
                size_t h = e >> 10, k = e & 1023;
                srcp = attn_W + h * H3 + k;
                dstp = g_Wab_hi + e;
            } else {               // Wd1: [512][512] from dec_W cols 0..511
                size_t e = (gw - 131072ull) * 4;
                size_t h = e >> 9, k = e & 511;
                srcp = dec_W + h * 1024 + k;
                dstp = g_Wd_hi + e;
            }
        }
        float4 v = *(const float4*)srcp;
        __half2 h01 = __floats2half2_rn(v.x, v.y);
        __half2 h23 = __floats2half2_rn(v.z, v.w);
        uint2 uh;
        uh.x = *reinterpret_cast<unsigned*>(&h01);
        uh.y = *reinterpret_cast<unsigned*>(&h23);
        *(uint2*)dstp = uh;
    }
}

// ============================================================================
// fp16 HMMA GEMM + fused v.tanh(.) reduce (single-term fp16), R9 shape.
// ============================================================================
template <int KSEG>
__global__ __launch_bounds__(256, 2) void gemm_fp16_kernel(
    const __half* __restrict__ W, int lda,
    const __half* __restrict__ st_hi, const __half* __restrict__ dy_hi,
    const float* __restrict__ addvec, const float* __restrict__ vvec,
    float* __restrict__ outp) {
    extern __shared__ char smch[];
    const uint32_t smb = smem_u32(smch);
    float* colacc = (float*)(smch + 2 * STAGE_HALVES * 2);

    const int tid = threadIdx.x;
    const int lane = tid & 31;
    const int wid = tid >> 5;
    const int wm = wid >> 2;   // 0..1
    const int wn = wid & 3;    // 0..3
    const int gid = lane >> 2; // 0..7
    const int lt4 = lane & 3;  // 0..3
    const int n0 = blockIdx.x * 128;
    const int b = blockIdx.y;

    const int NCH = KSEG * 16;

    const uint32_t a_lane = ((wm * 64 + (lane & 15)) * A_SH + (lane >> 4) * 8) * 2;
    const uint32_t b_lane = (BH_OFF + (lane & 15) * B_SH + wn * 32) * 2;

    float p0[4], p1[4];
#pragma unroll
    for (int nf = 0; nf < 4; nf++) { p0[nf] = 0.0f; p1[nf] = 0.0f; }

#pragma unroll 1
    for (int mt = 0; mt < 4; mt++) {
        float acc[4][4][4];
#pragma unroll
        for (int i = 0; i < 4; i++)
#pragma unroll
            for (int j = 0; j < 4; j++)
#pragma unroll
                for (int q = 0; q < 4; q++) acc[i][j][q] = 0.0f;

#define ISSUE_CHUNK(CH, STG) do { \
        int _kg = (CH) * TK; \
        const __half* _xh = (KSEG == 2 && _kg >= 512) ? dy_hi : st_hi; \
        int _kk = _kg & 511; \
        uint32_t _st = smb + (STG) * STAGE_HALVES * 2; \
        _Pragma("unroll") \
        for (int _i = 0; _i < 2; _i++) { \
            int _gi = _i * 256 + tid; \
            int _row = _gi >> 2, _g = _gi & 3; \
            cp16(_st + (_row * A_SH + _g * 8) * 2, \
                 W + (size_t)(mt * 128 + _row) * lda + _kg + _g * 8); \
        } \
        _Pragma("unroll") \
        for (int _i = 0; _i < 2; _i++) { \
            int _gi = _i * 256 + tid; \
            int _row = _gi >> 4, _g = _gi & 15; \
            cp16(_st + (BH_OFF + _row * B_SH + _g * 8) * 2, \
                 _xh + ((size_t)b * HH + _kk + _row) * SS + n0 + _g * 8); \
        } \
        CP_COMMIT(); \
    } while (0)

        ISSUE_CHUNK(0, 0);

#pragma unroll 1
        for (int ch = 0; ch < NCH; ch++) {
            if (ch + 1 < NCH) ISSUE_CHUNK(ch + 1, (ch + 1) & 1);
            if (ch + 1 < NCH) CP_WAIT(1); else CP_WAIT(0);
            __syncthreads();

            const uint32_t stb = smb + (ch & 1) * STAGE_HALVES * 2;
            const uint32_t a_addr = stb + a_lane;
            const uint32_t b_addr = stb + b_lane;

#pragma unroll
            for (int ks = 0; ks < 2; ks++) {
                const uint32_t ka = a_addr + ks * 32;
                const uint32_t kb = b_addr + ks * 16 * B_SH * 2;
                uint32_t ah[4][4], bh[4][2];
#pragma unroll
                for (int mf = 0; mf < 4; mf++)
                    ldm_x4(ah[mf], ka + mf * 16 * A_SH * 2);
#pragma unroll
                for (int nf = 0; nf < 4; nf++)
                    ldm_x2t(bh[nf], kb + nf * 16);
#pragma unroll
                for (int mf = 0; mf < 4; mf++)
#pragma unroll
                    for (int nf = 0; nf < 4; nf++)
                        mma_fp16(acc[mf][nf], ah[mf], bh[nf]);
            }
            __syncthreads();
        }

#pragma unroll
        for (int mf = 0; mf < 4; mf++) {
            int h0 = mt * 128 + wm * 64 + mf * 16 + gid;
            float vv0 = vvec[h0], vv1 = vvec[h0 + 8];
            float av0 = addvec[b * HH + h0], av1 = addvec[b * HH + h0 + 8];
#pragma unroll
            for (int nf = 0; nf < 4; nf++) {
                p0[nf] += vv0 * fast_tanh(acc[mf][nf][0] + av0)
                        + vv1 * fast_tanh(acc[mf][nf][2] + av1);
                p1[nf] += vv0 * fast_tanh(acc[mf][nf][1] + av0)
                        + vv1 * fast_tanh(acc[mf][nf][3] + av1);
            }
        }
    }

#pragma unroll
    for (int nf = 0; nf < 4; nf++) {
        float a0 = p0[nf], a1 = p1[nf];
#pragma unroll
        for (int d = 4; d < 32; d <<= 1) {
            a0 += __shfl_xor_sync(0xffffffffu, a0, d);
            a1 += __shfl_xor_sync(0xffffffffu, a1, d);
        }
        if (gid == 0) {
            int c = wm * 128 + wn * 32 + nf * 8 + lt4 * 2;
            colacc[c] = a0;
            colacc[c + 1] = a1;
        }
    }
    __syncthreads();
    if (tid < 128) outp[(size_t)b * SS + n0 + tid] = colacc[tid] + colacc[128 + tid];
#undef ISSUE_CHUNK
}

// ---------------- GRU: grid (2 h-tiles, 32 batch-tiles), 8 batches/CTA ----
__global__ __launch_bounds__(256) void gru_kernel(
    const float* __restrict__ last_output,
    const float* __restrict__ last_hidden,
    const float* __restrict__ emb_W,
    const float* __restrict__ emb_b,
    const float* __restrict__ Wih,
    const float* __restrict__ Whh,
    const float* __restrict__ bih,
    const float* __restrict__ bhh,
    float* __restrict__ hidden_out) {
    int ht = blockIdx.x;
    int b0 = blockIdx.y * 8;
    int t = threadIdx.x;
    __shared__ float sx[8][512], sh[8][512];

    for (int i = t; i < 4096; i += 256) {
        int bb = i >> 9, k = i & 511;
        int b = b0 + bb;
        sx[bb][k] = last_output[b * 2] * emb_W[k * 2]
                  + last_output[b * 2 + 1] * emb_W[k * 2 + 1] + emb_b[k];
        sh[bb][k] = last_hidden[b * HH + k];
    }
    __syncthreads();

    int h = ht * 256 + t;
    float r8[8], z8[8];

#pragma unroll 1
    for (int gate = 0; gate < 3; gate++) {
        int j = gate * HH + h;
        float ax[8], ahh[8];
        float bx = bih[j], bh2 = bhh[j];
#pragma unroll
        for (int bb = 0; bb < 8; bb++) { ax[bb] = bx; ahh[bb] = bh2; }
        const float4* wi = (const float4*)(Wih + (size_t)j * HH);
        const float4* wh = (const float4*)(Whh + (size_t)j * HH);
#pragma unroll 2
        for (int k4 = 0; k4 < 128; k4++) {
            float4 a = wi[k4];
            float4 c = wh[k4];
            int k = k4 * 4;
#pragma unroll
            for (int bb = 0; bb < 8; bb++) {
                ax[bb] += a.x * sx[bb][k] + a.y * sx[bb][k + 1]
                        + a.z * sx[bb][k + 2] + a.w * sx[bb][k + 3];
                ahh[bb] += c.x * sh[bb][k] + c.y * sh[bb][k + 1]
                         + c.z * sh[bb][k + 2] + c.w * sh[bb][k + 3];
            }
        }
        if (gate == 0) {
#pragma unroll
            for (int bb = 0; bb < 8; bb++) r8[bb] = my_sigmoid(ax[bb] + ahh[bb]);
        } else if (gate == 1) {
#pragma unroll
            for (int bb = 0; bb < 8; bb++) z8[bb] = my_sigmoid(ax[bb] + ahh[bb]);
        } else {
#pragma unroll
            for (int bb = 0; bb < 8; bb++) {
                float n = my_tanh(ax[bb] + r8[bb] * ahh[bb]);
                float hn = (1.0f - z8[bb]) * n + z8[bb] * sh[bb][h];
                g_hnew[(b0 + bb) * HH + h] = hn;
                hidden_out[(b0 + bb) * HH + h] = hn;
            }
        }
    }
}

// ---------------- matvec1: grid (8 h-tiles, 64 batch-tiles), 4 batches/CTA --
__global__ __launch_bounds__(256) void matvec_kernel(
    const float* __restrict__ M, int ldm, int off,
    const float* __restrict__ vec, float* __restrict__ out) {
    int b0 = blockIdx.y * 4;
    int h0 = blockIdx.x * 64;
    int t = threadIdx.x;
    __shared__ float sv[4][512];
    for (int i = t; i < 2048; i += 256) {
        int bb = i >> 9, k = i & 511;
        sv[bb][k] = vec[(b0 + bb) * HH + k];
    }
    __syncthreads();

    int hl = t >> 2, l4 = t & 3;
    int h = h0 + hl;
    const float* m = M + (size_t)h * ldm + off;
    float acc[4];
#pragma unroll
    for (int bb = 0; bb < 4; bb++) acc[bb] = 0.0f;
    for (int k = l4 * 4; k < HH; k += 16) {
        float4 mv = *(const float4*)(m + k);
#pragma unroll
        for (int bb = 0; bb < 4; bb++) {
            acc[bb] += mv.x * sv[bb][k] + mv.y * sv[bb][k + 1]
                     + mv.z * sv[bb][k + 2] + mv.w * sv[bb][k + 3];
        }
    }
#pragma unroll
    for (int bb = 0; bb < 4; bb++) {
        acc[bb] += __shfl_xor_sync(0xffffffffu, acc[bb], 1);
        acc[bb] += __shfl_xor_sync(0xffffffffu, acc[bb], 2);
    }
    if (l4 == 0) {
#pragma unroll
        for (int bb = 0; bb < 4; bb++) out[(b0 + bb) * HH + h] = acc[bb];
    }
}

// ---------------- fused softmax + context + matvec2 (one CTA per batch) ----
// cd2[b,h'] = sum_h ( softmax(scores[b,:]) @ st[b,h,:] )[h] * dec_W[h', 512+h]
__global__ __launch_bounds__(256) void fused_attn_kernel(
    const float* __restrict__ scores, const __half* __restrict__ sth,
    const float* __restrict__ dec_W, float* __restrict__ cd2) {
    int b = blockIdx.x;
    int t = threadIdx.x;
    int w = t >> 5, l = t & 31;
    __shared__ float sa[SS];    // attns
    __shared__ float sctx[HH];  // context
    __shared__ float red[256];

    // ---- softmax over scores[b, 0..511] ----
    float v0 = scores[b * SS + t];
    float v1 = scores[b * SS + 256 + t];
    red[t] = fmaxf(v0, v1);
    __syncthreads();
    for (int off = 128; off > 0; off >>= 1) {
        if (t < off) red[t] = fmaxf(red[t], red[t + off]);
        __syncthreads();
    }
    float mx = red[0];
    __syncthreads();
    float e0 = __expf(v0 - mx);
    float e1 = __expf(v1 - mx);
    red[t] = e0 + e1;
    __syncthreads();
    for (int off = 128; off > 0; off >>= 1) {
        if (t < off) red[t] += red[t + off];
        __syncthreads();
    }
    float inv = 1.0f / red[0];
    sa[t] = e0 * inv;
    sa[256 + t] = e1 * inv;
    __syncthreads();

    // ---- context: warp w covers h rows [w*64, w*64+64), 2 rows at a time ----
    const __half* stb = sth + (size_t)b * HH * SS;
#pragma unroll 1
    for (int hh = 0; hh < 64; hh += 2) {
        int h0 = w * 64 + hh;
        const __half* r0 = stb + (size_t)h0 * SS;
        const __half* r1 = r0 + SS;
        float a0 = 0.0f, a1 = 0.0f;
        for (int s = l * 8; s < SS; s += 256) {
            uint4 q0 = *(const uint4*)(r0 + s);
            uint4 q1 = *(const uint4*)(r1 + s);
            const __half2* p0 = (const __half2*)&q0;
            const __half2* p1 = (const __half2*)&q1;
#pragma unroll
            for (int q = 0; q < 4; q++) {
                float2 f0 = __half22float2(p0[q]);
                float2 f1 = __half22float2(p1[q]);
                a0 += f0.x * sa[s + q * 2] + f0.y * sa[s + q * 2 + 1];
                a1 += f1.x * sa[s + q * 2] + f1.y * sa[s + q * 2 + 1];
            }
        }
#pragma unroll
        for (int off = 16; off > 0; off >>= 1) {
            a0 += __shfl_xor_sync(0xffffffffu, a0, off);
            a1 += __shfl_xor_sync(0xffffffffu, a1, off);
        }
        if (l == 0) { sctx[h0] = a0; sctx[h0 + 1] = a1; }
    }
    __syncthreads();

    // ---- matvec2: cd2[b,h'] = sum_k sctx[k] * dec_W[h', 512+k] ----
    int hl = t >> 2, l4 = t & 3;
#pragma unroll 1
    for (int r = 0; r < 8; r++) {
        int h = r * 64 + hl;
        const float* m = dec_W + (size_t)h * 1024 + 512;
        float acc = 0.0f;
        for (int k = l4 * 4; k < HH; k += 16) {
            float4 mv = *(const float4*)(m + k);
            acc += mv.x * sctx[k] + mv.y * sctx[k + 1]
                 + mv.z * sctx[k + 2] + mv.w * sctx[k + 3];
        }
        acc += __shfl_xor_sync(0xffffffffu, acc, 1);
        acc += __shfl_xor_sync(0xffffffffu, acc, 2);
        if (l4 == 0) cd2[b * HH + h] = acc;
    }
}

// ---------------- launch (single stream) ----------------
extern "C" void kernel_launch(void* const* d_in, const int* in_sizes, int n_in,
                              void* d_out, int out_size) {
    const float* st     = (const float*)d_in[0];
    const float* dy     = (const float*)d_in[1];
    const float* lo     = (const float*)d_in[2];
    const float* lh     = (const float*)d_in[3];
    const float* embW   = (const float*)d_in[4];
    const float* embb   = (const float*)d_in[5];
    const float* Wih    = (const float*)d_in[6];
    const float* Whh    = (const float*)d_in[7];
    const float* bih    = (const float*)d_in[8];
    const float* bhh    = (const float*)d_in[9];
    const float* attn_v = (const float*)d_in[10];
    const float* attn_W = (const float*)d_in[11];
    const float* dec_v  = (const float*)d_in[12];
    const float* dec_W  = (const float*)d_in[13];
    float* out = (float*)d_out;

    float *p_hnew, *p_hc, *p_scores, *p_cd2;
    cudaGetSymbolAddress((void**)&p_hnew, g_hnew);
    cudaGetSymbolAddress((void**)&p_hc, g_hc);
    cudaGetSymbolAddress((void**)&p_scores, g_scores);
    cudaGetSymbolAddress((void**)&p_cd2, g_cd2);

    __half *psth, *pdyh, *pWabh, *pWdh;
    cudaGetSymbolAddress((void**)&psth, g_st_hi);
    cudaGetSymbolAddress((void**)&pdyh, g_dy_hi);
    cudaGetSymbolAddress((void**)&pWabh, g_Wab_hi);
    cudaGetSymbolAddress((void**)&pWdh, g_Wd_hi);

    cudaFuncSetAttribute(gemm_fp16_kernel<2>,
                         cudaFuncAttributeMaxDynamicSharedMemorySize, SMEM_BYTES);
    cudaFuncSetAttribute(gemm_fp16_kernel<1>,
                         cudaFuncAttributeMaxDynamicSharedMemorySize, SMEM_BYTES);

    prep_all<<<4096, 256>>>(st, dy, attn_W, dec_W);

    gru_kernel<<<dim3(2, 32), 256>>>(lo, lh, embW, embb, Wih, Whh, bih, bhh,
                                     out + BB * SS);

    matvec_kernel<<<dim3(8, 64), 256>>>(attn_W, H3, 2 * HH, p_hnew, p_hc);

    gemm_fp16_kernel<2><<<dim3(4, BB), 256, SMEM_BYTES>>>(
        pWabh, 1024, psth, pdyh, p_hc, attn_v, p_scores);

    fused_attn_kernel<<<BB, 256>>>(p_scores, psth, dec_W, p_cd2);

    gemm_fp16_kernel<1><<<dim3(4, BB), 256, SMEM_BYTES>>>(
        pWdh, 512, psth, psth, p_cd2, dec_v, out);
}

// round 14
// speedup vs baseline: 1.1250x; 1.1250x over previous
#include <cuda_runtime.h>
#include <cuda_fp16.h>
#include <cstdint>

#define BB 256
#define HH 512
#define SS 512
#define H3 1536

// ---------------- scratch ----------------
__device__ float g_hnew[BB * HH];
__device__ float g_hc[BB * HH];
__device__ float g_scores[BB * SS];
__device__ float g_attns[BB * SS];
__device__ float g_context[BB * HH];
__device__ float g_cd2[BB * HH];

// pre-converted fp16 operands
__device__ __half g_st_hi[BB * HH * SS];
__device__ __half g_dy_hi[BB * HH * SS];
__device__ __half g_Wab_hi[HH * 1024];
__device__ __half g_Wd_hi[HH * HH];

// ---------------- math ----------------
__device__ __forceinline__ float my_tanh(float x) {
    float ax = fabsf(x);
    float e = __expf(-2.0f * ax);
    float r = __fdividef(1.0f - e, 1.0f + e);
    return copysignf(r, x);
}
__device__ __forceinline__ float fast_tanh(float x) {
    float r;
    asm("tanh.approx.f32 %0, %1;" : "=f"(r) : "f"(x));
    return r;
}
__device__ __forceinline__ float my_sigmoid(float x) {
    return 1.0f / (1.0f + __expf(-x));
}

// ---------------- PTX helpers ----------------
__device__ __forceinline__ uint32_t smem_u32(const void* p) {
    uint32_t a;
    asm("{ .reg .u64 t; cvta.to.shared.u64 t, %1; cvt.u32.u64 %0, t; }" : "=r"(a) : "l"(p));
    return a;
}
__device__ __forceinline__ void cp16(uint32_t dst, const void* src) {
    asm volatile("cp.async.cg.shared.global [%0], [%1], 16;" :: "r"(dst), "l"(src));
}
#define CP_COMMIT() asm volatile("cp.async.commit_group;" ::: "memory")
#define CP_WAIT(n)  asm volatile("cp.async.wait_group %0;" :: "n"(n) : "memory")

__device__ __forceinline__ void ldm_x4(uint32_t* r, uint32_t a) {
    asm volatile("ldmatrix.sync.aligned.m8n8.x4.shared.b16 {%0,%1,%2,%3}, [%4];"
        : "=r"(r[0]), "=r"(r[1]), "=r"(r[2]), "=r"(r[3]) : "r"(a));
}
__device__ __forceinline__ void ldm_x2t(uint32_t* r, uint32_t a) {
    asm volatile("ldmatrix.sync.aligned.m8n8.x2.trans.shared.b16 {%0,%1}, [%2];"
        : "=r"(r[0]), "=r"(r[1]) : "r"(a));
}
__device__ __forceinline__ void mma_fp16(float* d, const uint32_t* a, const uint32_t* b) {
    asm volatile(
        "mma.sync.aligned.m16n8k16.row.col.f32.f16.f16.f32 "
        "{%0,%1,%2,%3}, {%4,%5,%6,%7}, {%8,%9}, {%0,%1,%2,%3};"
        : "+f"(d[0]), "+f"(d[1]), "+f"(d[2]), "+f"(d[3])
        : "r"(a[0]), "r"(a[1]), "r"(a[2]), "r"(a[3]), "r"(b[0]), "r"(b[1]));
}

// ---------------- tile config (units: fp16 halves) ----------------
// CTA 128m x 128n, warp 64m x 32n, TK=32, 4-stage cp.async pipeline, occ 2.
#define TK 32
#define NSTG 4
#define A_SH 40
#define B_SH 136
#define A_HALVES (128 * A_SH)           /* 5120 */
#define B_HALVES (TK * B_SH)            /* 4352 */
#define BH_OFF A_HALVES
#define STAGE_HALVES (A_HALVES + B_HALVES) /* 9472 */
#define SMEM_BYTES (NSTG * STAGE_HALVES * 2 + 256 * 4) /* 76800 */

// ---------------- prep: all fp32->fp16 conversions in one pass ----------------
__global__ void prep_all(const float* __restrict__ st, const float* __restrict__ dy,
                         const float* __restrict__ attn_W,
                         const float* __restrict__ dec_W) {
    const size_t NGE = 2ull * 16777216ull;
    const size_t NGW = 196608ull;
    size_t nth = (size_t)gridDim.x * blockDim.x;
    for (size_t g = (size_t)blockIdx.x * blockDim.x + threadIdx.x; g < NGE + NGW;
         g += nth) {
        const float* srcp;
        __half* dstp;
        if (g < NGE) {
            bool isdy = g >= 16777216ull;
            size_t off = (g & 16777215ull) * 4;
            srcp = (isdy ? dy : st) + off;
            dstp = (isdy ? g_dy_hi : g_st_hi) + off;
        } else {
            size_t gw = g - NGE;
            if (gw < 131072ull) {
                size_t e = gw * 4;
                size_t h = e >> 10, k = e & 1023;
                srcp = attn_W + h * H3 + k;
                dstp = g_Wab_hi + e;
            } else {
                size_t e = (gw - 131072ull) * 4;
                size_t h = e >> 9, k = e & 511;
                srcp = dec_W + h * 1024 + k;
                dstp = g_Wd_hi + e;
            }
        }
        float4 v = *(const float4*)srcp;
        __half2 h01 = __floats2half2_rn(v.x, v.y);
        __half2 h23 = __floats2half2_rn(v.z, v.w);
        uint2 uh;
        uh.x = *reinterpret_cast<unsigned*>(&h01);
        uh.y = *reinterpret_cast<unsigned*>(&h23);
        *(uint2*)dstp = uh;
    }
}

// ============================================================================
// fp16 HMMA GEMM + fused v.tanh(.) reduce — 4-stage pipeline, 1 sync/chunk.
// ============================================================================
template <int KSEG>
__global__ __launch_bounds__(256, 2) void gemm_fp16_kernel(
    const __half* __restrict__ W, int lda,
    const __half* __restrict__ st_hi, const __half* __restrict__ dy_hi,
    const float* __restrict__ addvec, const float* __restrict__ vvec,
    float* __restrict__ outp) {
    extern __shared__ char smch[];
    const uint32_t smb = smem_u32(smch);
    float* colacc = (float*)(smch + NSTG * STAGE_HALVES * 2);

    const int tid = threadIdx.x;
    const int lane = tid & 31;
    const int wid = tid >> 5;
    const int wm = wid >> 2;   // 0..1
    const int wn = wid & 3;    // 0..3
    const int gid = lane >> 2; // 0..7
    const int lt4 = lane & 3;  // 0..3
    const int n0 = blockIdx.x * 128;
    const int b = blockIdx.y;

    const int NCH = KSEG * 16;

    const uint32_t a_lane = ((wm * 64 + (lane & 15)) * A_SH + (lane >> 4) * 8) * 2;
    const uint32_t b_lane = (BH_OFF + (lane & 15) * B_SH + wn * 32) * 2;

    float p0[4], p1[4];
#pragma unroll
    for (int nf = 0; nf < 4; nf++) { p0[nf] = 0.0f; p1[nf] = 0.0f; }

#pragma unroll 1
    for (int mt = 0; mt < 4; mt++) {
        float acc[4][4][4];
#pragma unroll
        for (int i = 0; i < 4; i++)
#pragma unroll
            for (int j = 0; j < 4; j++)
#pragma unroll
                for (int q = 0; q < 4; q++) acc[i][j][q] = 0.0f;

#define ISSUE_CHUNK(CH, STG) do { \
        int _kg = (CH) * TK; \
        const __half* _xh = (KSEG == 2 && _kg >= 512) ? dy_hi : st_hi; \
        int _kk = _kg & 511; \
        uint32_t _st = smb + (STG) * STAGE_HALVES * 2; \
        _Pragma("unroll") \
        for (int _i = 0; _i < 2; _i++) { \
            int _gi = _i * 256 + tid; \
            int _row = _gi >> 2, _g = _gi & 3; \
            cp16(_st + (_row * A_SH + _g * 8) * 2, \
                 W + (size_t)(mt * 128 + _row) * lda + _kg + _g * 8); \
        } \
        _Pragma("unroll") \
        for (int _i = 0; _i < 2; _i++) { \
            int _gi = _i * 256 + tid; \
            int _row = _gi >> 4, _g = _gi & 15; \
            cp16(_st + (BH_OFF + _row * B_SH + _g * 8) * 2, \
                 _xh + ((size_t)b * HH + _kk + _row) * SS + n0 + _g * 8); \
        } \
        CP_COMMIT(); \
    } while (0)

        // prologue: 3 chunks in flight
        ISSUE_CHUNK(0, 0);
        ISSUE_CHUNK(1, 1);
        ISSUE_CHUNK(2, 2);

#pragma unroll 1
        for (int ch = 0; ch < NCH; ch++) {
            // wait for chunk ch: pending-after = #committed - (ch+1)
            if (ch < NCH - 2)      CP_WAIT(2);
            else if (ch == NCH - 2) CP_WAIT(1);
            else                    CP_WAIT(0);
            __syncthreads();   // single barrier per chunk

            const uint32_t stb = smb + (ch & (NSTG - 1)) * STAGE_HALVES * 2;
            const uint32_t a_addr = stb + a_lane;
            const uint32_t b_addr = stb + b_lane;

#pragma unroll
            for (int ks = 0; ks < 2; ks++) {
                const uint32_t ka = a_addr + ks * 32;
                const uint32_t kb = b_addr + ks * 16 * B_SH * 2;
                uint32_t ah[4][4], bh[4][2];
#pragma unroll
                for (int mf = 0; mf < 4; mf++)
                    ldm_x4(ah[mf], ka + mf * 16 * A_SH * 2);
#pragma unroll
                for (int nf = 0; nf < 4; nf++)
                    ldm_x2t(bh[nf], kb + nf * 16);
#pragma unroll
                for (int mf = 0; mf < 4; mf++)
#pragma unroll
                    for (int nf = 0; nf < 4; nf++)
                        mma_fp16(acc[mf][nf], ah[mf], bh[nf]);
            }

            // prefetch chunk ch+3 into stage (ch+3)%4 = (ch-1)%4 — its readers
            // (iteration ch-1) all passed this iteration's barrier already.
            if (ch + 3 < NCH) ISSUE_CHUNK(ch + 3, (ch + 3) & (NSTG - 1));
        }

        // ---- epilogue for this m-tile (registers only) ----
#pragma unroll
        for (int mf = 0; mf < 4; mf++) {
            int h0 = mt * 128 + wm * 64 + mf * 16 + gid;
            float vv0 = vvec[h0], vv1 = vvec[h0 + 8];
            float av0 = addvec[b * HH + h0], av1 = addvec[b * HH + h0 + 8];
#pragma unroll
            for (int nf = 0; nf < 4; nf++) {
                p0[nf] += vv0 * fast_tanh(acc[mf][nf][0] + av0)
                        + vv1 * fast_tanh(acc[mf][nf][2] + av1);
                p1[nf] += vv0 * fast_tanh(acc[mf][nf][1] + av0)
                        + vv1 * fast_tanh(acc[mf][nf][3] + av1);
            }
        }
        __syncthreads();  // all warps done with stage buffers before next mt prologue
    }

#pragma unroll
    for (int nf = 0; nf < 4; nf++) {
        float a0 = p0[nf], a1 = p1[nf];
#pragma unroll
        for (int d = 4; d < 32; d <<= 1) {
            a0 += __shfl_xor_sync(0xffffffffu, a0, d);
            a1 += __shfl_xor_sync(0xffffffffu, a1, d);
        }
        if (gid == 0) {
            int c = wm * 128 + wn * 32 + nf * 8 + lt4 * 2;
            colacc[c] = a0;
            colacc[c + 1] = a1;
        }
    }
    __syncthreads();
    if (tid < 128) outp[(size_t)b * SS + n0 + tid] = colacc[tid] + colacc[128 + tid];
#undef ISSUE_CHUNK
}

// ---------------- GRU: grid (2 h-tiles, 32 batch-tiles), 8 batches/CTA ----
__global__ __launch_bounds__(256) void gru_kernel(
    const float* __restrict__ last_output,
    const float* __restrict__ last_hidden,
    const float* __restrict__ emb_W,
    const float* __restrict__ emb_b,
    const float* __restrict__ Wih,
    const float* __restrict__ Whh,
    const float* __restrict__ bih,
    const float* __restrict__ bhh,
    float* __restrict__ hidden_out) {
    int ht = blockIdx.x;
    int b0 = blockIdx.y * 8;
    int t = threadIdx.x;
    __shared__ float sx[8][512], sh[8][512];

    for (int i = t; i < 4096; i += 256) {
        int bb = i >> 9, k = i & 511;
        int b = b0 + bb;
        sx[bb][k] = last_output[b * 2] * emb_W[k * 2]
                  + last_output[b * 2 + 1] * emb_W[k * 2 + 1] + emb_b[k];
        sh[bb][k] = last_hidden[b * HH + k];
    }
    __syncthreads();

    int h = ht * 256 + t;
    float r8[8], z8[8];

#pragma unroll 1
    for (int gate = 0; gate < 3; gate++) {
        int j = gate * HH + h;
        float ax[8], ahh[8];
        float bx = bih[j], bh2 = bhh[j];
#pragma unroll
        for (int bb = 0; bb < 8; bb++) { ax[bb] = bx; ahh[bb] = bh2; }
        const float4* wi = (const float4*)(Wih + (size_t)j * HH);
        const float4* wh = (const float4*)(Whh + (size_t)j * HH);
#pragma unroll 2
        for (int k4 = 0; k4 < 128; k4++) {
            float4 a = wi[k4];
            float4 c = wh[k4];
            int k = k4 * 4;
#pragma unroll
            for (int bb = 0; bb < 8; bb++) {
                ax[bb] += a.x * sx[bb][k] + a.y * sx[bb][k + 1]
                        + a.z * sx[bb][k + 2] + a.w * sx[bb][k + 3];
                ahh[bb] += c.x * sh[bb][k] + c.y * sh[bb][k + 1]
                         + c.z * sh[bb][k + 2] + c.w * sh[bb][k + 3];
            }
        }
        if (gate == 0) {
#pragma unroll
            for (int bb = 0; bb < 8; bb++) r8[bb] = my_sigmoid(ax[bb] + ahh[bb]);
        } else if (gate == 1) {
#pragma unroll
            for (int bb = 0; bb < 8; bb++) z8[bb] = my_sigmoid(ax[bb] + ahh[bb]);
        } else {
#pragma unroll
            for (int bb = 0; bb < 8; bb++) {
                float n = my_tanh(ax[bb] + r8[bb] * ahh[bb]);
                float hn = (1.0f - z8[bb]) * n + z8[bb] * sh[bb][h];
                g_hnew[(b0 + bb) * HH + h] = hn;
                hidden_out[(b0 + bb) * HH + h] = hn;
            }
        }
    }
}

// ---------------- matvec: grid (8 h-tiles, 64 batch-tiles), 4 batches/CTA --
__global__ __launch_bounds__(256) void matvec_kernel(
    const float* __restrict__ M, int ldm, int off,
    const float* __restrict__ vec, float* __restrict__ out) {
    int b0 = blockIdx.y * 4;
    int h0 = blockIdx.x * 64;
    int t = threadIdx.x;
    __shared__ float sv[4][512];
    for (int i = t; i < 2048; i += 256) {
        int bb = i >> 9, k = i & 511;
        sv[bb][k] = vec[(b0 + bb) * HH + k];
    }
    __syncthreads();

    int hl = t >> 2, l4 = t & 3;
    int h = h0 + hl;
    const float* m = M + (size_t)h * ldm + off;
    float acc[4];
#pragma unroll
    for (int bb = 0; bb < 4; bb++) acc[bb] = 0.0f;
    for (int k = l4 * 4; k < HH; k += 16) {
        float4 mv = *(const float4*)(m + k);
#pragma unroll
        for (int bb = 0; bb < 4; bb++) {
            acc[bb] += mv.x * sv[bb][k] + mv.y * sv[bb][k + 1]
                     + mv.z * sv[bb][k + 2] + mv.w * sv[bb][k + 3];
        }
    }
#pragma unroll
    for (int bb = 0; bb < 4; bb++) {
        acc[bb] += __shfl_xor_sync(0xffffffffu, acc[bb], 1);
        acc[bb] += __shfl_xor_sync(0xffffffffu, acc[bb], 2);
    }
    if (l4 == 0) {
#pragma unroll
        for (int bb = 0; bb < 4; bb++) out[(b0 + bb) * HH + h] = acc[bb];
    }
}

// ---------------- softmax ----------------
__global__ void softmax_kernel(const float* __restrict__ scores,
                               float* __restrict__ attns) {
    int b = blockIdx.x;
    int t = threadIdx.x;
    __shared__ float sm[256];
    float v0 = scores[b * SS + t];
    float v1 = scores[b * SS + 256 + t];
    sm[t] = fmaxf(v0, v1);
    __syncthreads();
    for (int off = 128; off > 0; off >>= 1) {
        if (t < off) sm[t] = fmaxf(sm[t], sm[t + off]);
        __syncthreads();
    }
    float mx = sm[0];
    __syncthreads();
    float e0 = __expf(v0 - mx);
    float e1 = __expf(v1 - mx);
    sm[t] = e0 + e1;
    __syncthreads();
    for (int off = 128; off > 0; off >>= 1) {
        if (t < off) sm[t] += sm[t + off];
        __syncthreads();
    }
    float inv = 1.0f / sm[0];
    attns[b * SS + t] = e0 * inv;
    attns[b * SS + 256 + t] = e1 * inv;
}

// ---------------- context (reads fp16 st) ----------------
__global__ void context_kernel(const __half* __restrict__ sth,
                               const float* __restrict__ attns,
                               float* __restrict__ ctx) {
    int b = blockIdx.y;
    int h0 = blockIdx.x * 8;
    int w = threadIdx.x >> 5, l = threadIdx.x & 31;
    __shared__ float sa[SS];
    for (int s = threadIdx.x; s < SS; s += 256) sa[s] = attns[b * SS + s];
    __syncthreads();
    int h = h0 + w;
    const __half* row = sth + (size_t)b * HH * SS + (size_t)h * SS;
    float acc = 0.0f;
    for (int s = l * 8; s < SS; s += 256) {
        uint4 r4 = *(const uint4*)(row + s);
        const __half2* hp = (const __half2*)&r4;
#pragma unroll
        for (int q = 0; q < 4; q++) {
            float2 f = __half22float2(hp[q]);
            acc += f.x * sa[s + q * 2] + f.y * sa[s + q * 2 + 1];
        }
    }
#pragma unroll
    for (int off = 16; off > 0; off >>= 1)
        acc += __shfl_xor_sync(0xffffffffu, acc, off);
    if (l == 0) ctx[b * HH + h] = acc;
}

// ---------------- launch (single stream) ----------------
extern "C" void kernel_launch(void* const* d_in, const int* in_sizes, int n_in,
                              void* d_out, int out_size) {
    const float* st     = (const float*)d_in[0];
    const float* dy     = (const float*)d_in[1];
    const float* lo     = (const float*)d_in[2];
    const float* lh     = (const float*)d_in[3];
    const float* embW   = (const float*)d_in[4];
    const float* embb   = (const float*)d_in[5];
    const float* Wih    = (const float*)d_in[6];
    const float* Whh    = (const float*)d_in[7];
    const float* bih    = (const float*)d_in[8];
    const float* bhh    = (const float*)d_in[9];
    const float* attn_v = (const float*)d_in[10];
    const float* attn_W = (const float*)d_in[11];
    const float* dec_v  = (const float*)d_in[12];
    const float* dec_W  = (const float*)d_in[13];
    float* out = (float*)d_out;

    float *p_hnew, *p_hc, *p_scores, *p_attns, *p_ctx, *p_cd2;
    cudaGetSymbolAddress((void**)&p_hnew, g_hnew);
    cudaGetSymbolAddress((void**)&p_hc, g_hc);
    cudaGetSymbolAddress((void**)&p_scores, g_scores);
    cudaGetSymbolAddress((void**)&p_attns, g_attns);
    cudaGetSymbolAddress((void**)&p_ctx, g_context);
    cudaGetSymbolAddress((void**)&p_cd2, g_cd2);

    __half *psth, *pdyh, *pWabh, *pWdh;
    cudaGetSymbolAddress((void**)&psth, g_st_hi);
    cudaGetSymbolAddress((void**)&pdyh, g_dy_hi);
    cudaGetSymbolAddress((void**)&pWabh, g_Wab_hi);
    cudaGetSymbolAddress((void**)&pWdh, g_Wd_hi);

    cudaFuncSetAttribute(gemm_fp16_kernel<2>,
                         cudaFuncAttributeMaxDynamicSharedMemorySize, SMEM_BYTES);
    cudaFuncSetAttribute(gemm_fp16_kernel<1>,
                         cudaFuncAttributeMaxDynamicSharedMemorySize, SMEM_BYTES);

    prep_all<<<4096, 256>>>(st, dy, attn_W, dec_W);

    gru_kernel<<<dim3(2, 32), 256>>>(lo, lh, embW, embb, Wih, Whh, bih, bhh,
                                     out + BB * SS);

    matvec_kernel<<<dim3(8, 64), 256>>>(attn_W, H3, 2 * HH, p_hnew, p_hc);

    gemm_fp16_kernel<2><<<dim3(4, BB), 256, SMEM_BYTES>>>(
        pWabh, 1024, psth, pdyh, p_hc, attn_v, p_scores);

    softmax_kernel<<<BB, 256>>>(p_scores, p_attns);
    context_kernel<<<dim3(HH / 8, BB), 256>>>(psth, p_attns, p_ctx);

    matvec_kernel<<<dim3(8, 64), 256>>>(dec_W, 2 * HH, HH, p_ctx, p_cd2);

    gemm_fp16_kernel<1><<<dim3(4, BB), 256, SMEM_BYTES>>>(
        pWdh, 512, psth, psth, p_cd2, dec_v, out);
}